// round 1
// baseline (speedup 1.0000x reference)
#include <cuda_runtime.h>

#define BB 256
#define SS 4096
#define HH 64
#define NG 256   // 4*H gates

// Layer ping-pong scratch (allocation-free: static device globals)
__device__ float g_buf0[(size_t)BB * SS * HH];
__device__ float g_buf1[(size_t)BB * SS * HH];

// ---- packed f32x2 helpers (FFMA2 path, sm_103a) ----
__device__ __forceinline__ unsigned long long pk2(float lo, float hi) {
    unsigned long long r;
    asm("mov.b64 %0,{%1,%2};" : "=l"(r) : "f"(lo), "f"(hi));
    return r;
}
__device__ __forceinline__ void upk2(unsigned long long v, float& lo, float& hi) {
    asm("mov.b64 {%0,%1},%2;" : "=f"(lo), "=f"(hi) : "l"(v));
}
__device__ __forceinline__ unsigned long long ffma2(unsigned long long a,
                                                    unsigned long long b,
                                                    unsigned long long c) {
    unsigned long long d;
    asm("fma.rn.f32x2 %0,%1,%2,%3;" : "=l"(d) : "l"(a), "l"(b), "l"(c));
    return d;
}

// Activations: MUFU.EX2 + MUFU.RCP based (err ~1e-6, well under 1e-3 budget)
__device__ __forceinline__ float sig_(float x) {
    float e = __expf(-x);
    return __fdividef(1.f, 1.f + e);
}
__device__ __forceinline__ float tanh_(float x) {
    float e = __expf(-2.f * x);
    return __fdividef(2.f, 1.f + e) - 1.f;
}

// One LSTM layer scan. Grid: 128 CTAs x 256 threads. CTA owns batch rows
// (2*blockIdx.x, 2*blockIdx.x+1) for all 4096 steps. Thread j owns gate j
// (PyTorch order i,f,g,o), with its full weight row held in registers as
// packed f32x2. Input vector + h vector broadcast from SMEM.
template <bool L0>
__global__ __launch_bounds__(256, 1)
void lstm_scan(const float* __restrict__ xin,
               const float* __restrict__ Wih, const float* __restrict__ Whh,
               const float* __restrict__ bih, const float* __restrict__ bhh,
               float* __restrict__ hsout,
               float* __restrict__ hn, float* __restrict__ cn) {
    const int j = threadIdx.x;       // gate index 0..255
    const int b0 = blockIdx.x * 2;   // global batch base

    __shared__ float4 sh_x[2][2][16];  // [parity][batch][64 floats] (layers 1,2)
    __shared__ float  sh_xs[2][2];     // [parity][batch] scalar x (layer 0)
    __shared__ float4 sh_h[2][16];     // [batch][64 floats] h_{t-1}
    __shared__ float  sh_act[2][NG];   // activated gates per batch

    // ---- weights into registers ----
    unsigned long long whh[32];
    unsigned long long wih[32];
    float w0 = 0.f;
    {
        const float4* Wr = reinterpret_cast<const float4*>(Whh + j * HH);
#pragma unroll
        for (int k = 0; k < 16; k++) {
            float4 v = Wr[k];
            whh[2 * k] = pk2(v.x, v.y);
            whh[2 * k + 1] = pk2(v.z, v.w);
        }
    }
    if (!L0) {
        const float4* Wr = reinterpret_cast<const float4*>(Wih + j * HH);
#pragma unroll
        for (int k = 0; k < 16; k++) {
            float4 v = Wr[k];
            wih[2 * k] = pk2(v.x, v.y);
            wih[2 * k + 1] = pk2(v.z, v.w);
        }
    } else {
        w0 = Wih[j];  // Wih0 is [256,1]
    }
    const float bias = bih[j] + bhh[j];

    // ---- init: h=0, prime x pipeline ----
    if (j < 32) reinterpret_cast<float4*>(sh_h)[j] = make_float4(0.f, 0.f, 0.f, 0.f);

    float4 xpre = make_float4(0.f, 0.f, 0.f, 0.f);
    float xpres = 0.f;
    int lb = 0, li = 0;
    size_t xbase4 = 0, xbase1 = 0;
    if (!L0) {
        if (j < 32) {
            lb = j >> 4;
            li = j & 15;
            xbase4 = ((size_t)(b0 + lb)) * SS * 16;
            const float4* xg = reinterpret_cast<const float4*>(xin);
            sh_x[0][lb][li] = xg[xbase4 + li];            // x_0
            xpre = xg[xbase4 + 16 + li];                  // x_1
        }
    } else {
        if (j < 2) {
            xbase1 = ((size_t)(b0 + j)) * SS;
            sh_xs[0][j] = xin[xbase1];                    // x_0
            xpres = xin[xbase1 + 1];                      // x_1
        }
    }

    float c_state = 0.f;
    __syncthreads();

    for (int t = 0; t < SS; ++t) {
        const int p = t & 1;

        // [A] stage x_{t+1} into other parity slot; prefetch x_{t+2}
        if (!L0) {
            if (j < 32) {
                sh_x[p ^ 1][lb][li] = xpre;
                if (t + 2 < SS) {
                    const float4* xg = reinterpret_cast<const float4*>(xin);
                    xpre = xg[xbase4 + (size_t)(t + 2) * 16 + li];
                }
            }
        } else {
            if (j < 2) {
                sh_xs[p ^ 1][j] = xpres;
                if (t + 2 < SS) xpres = xin[xbase1 + t + 2];
            }
        }

        // [B] gate pre-activations: g = bias + Wih·x_t + Whh·h_{t-1}
        unsigned long long a0 = pk2(bias, 0.f);
        unsigned long long a1 = pk2(bias, 0.f);
        const ulonglong2* vh = reinterpret_cast<const ulonglong2*>(sh_h);
        if (!L0) {
            const ulonglong2* vx = reinterpret_cast<const ulonglong2*>(sh_x[p]);
#pragma unroll
            for (int k = 0; k < 16; k++) {
                ulonglong2 x0 = vx[k];
                ulonglong2 x1 = vx[16 + k];
                a0 = ffma2(wih[2 * k], x0.x, a0);
                a0 = ffma2(wih[2 * k + 1], x0.y, a0);
                a1 = ffma2(wih[2 * k], x1.x, a1);
                a1 = ffma2(wih[2 * k + 1], x1.y, a1);
            }
        }
#pragma unroll
        for (int k = 0; k < 16; k++) {
            ulonglong2 h0 = vh[k];
            ulonglong2 h1 = vh[16 + k];
            a0 = ffma2(whh[2 * k], h0.x, a0);
            a0 = ffma2(whh[2 * k + 1], h0.y, a0);
            a1 = ffma2(whh[2 * k], h1.x, a1);
            a1 = ffma2(whh[2 * k + 1], h1.y, a1);
        }
        float lo0, hi0, lo1, hi1;
        upk2(a0, lo0, hi0);
        upk2(a1, lo1, hi1);
        float g0 = lo0 + hi0;
        float g1 = lo1 + hi1;
        if (L0) {
            g0 = fmaf(sh_xs[p][0], w0, g0);
            g1 = fmaf(sh_xs[p][1], w0, g1);
        }
        float A0, A1;
        if ((j >> 6) == 2) {  // 'g' gate -> tanh; i,f,o -> sigmoid
            A0 = tanh_(g0);
            A1 = tanh_(g1);
        } else {
            A0 = sig_(g0);
            A1 = sig_(g1);
        }
        sh_act[0][j] = A0;
        sh_act[1][j] = A1;

        __syncthreads();  // [C] gates ready

        // [D] state update: threads 0..127 own one (batch, hidden) each
        if (j < 128) {
            const int b = j >> 6, h = j & 63;
            const float* A = sh_act[b];
            float iv = A[h];
            float fv = A[64 + h];
            float gv = A[128 + h];
            float ov = A[192 + h];
            c_state = fv * c_state + iv * gv;
            float hv = ov * tanh_(c_state);
            reinterpret_cast<float*>(sh_h)[b * HH + h] = hv;
            hsout[((size_t)(b0 + b) * SS + t) * HH + h] = hv;
            if (t == SS - 1) {
                hn[(b0 + b) * HH + h] = hv;
                cn[(b0 + b) * HH + h] = c_state;
            }
        }
        __syncthreads();  // [E] h visible for next step
    }
}

// Final projection: y[b,s] = hs2[b,s,:]·Wlin + blin. One warp per output.
__global__ __launch_bounds__(256)
void proj_kernel(const float* __restrict__ hs, const float* __restrict__ Wlin,
                 const float* __restrict__ blin, float* __restrict__ y) {
    const int gw = (blockIdx.x * 256 + threadIdx.x) >> 5;  // output index, exact grid
    const int lane = threadIdx.x & 31;
    float2 w = reinterpret_cast<const float2*>(Wlin)[lane];
    float2 v = reinterpret_cast<const float2*>(hs + (size_t)gw * HH)[lane];
    float p = v.x * w.x + v.y * w.y;
#pragma unroll
    for (int o = 16; o; o >>= 1) p += __shfl_xor_sync(0xffffffffu, p, o);
    if (lane == 0) y[gw] = p + blin[0];
}

extern "C" void kernel_launch(void* const* d_in, const int* in_sizes, int n_in,
                              void* d_out, int out_size) {
    const float* x    = (const float*)d_in[0];
    const float* Wih0 = (const float*)d_in[1];
    const float* Whh0 = (const float*)d_in[2];
    const float* bih0 = (const float*)d_in[3];
    const float* bhh0 = (const float*)d_in[4];
    const float* Wih1 = (const float*)d_in[5];
    const float* Whh1 = (const float*)d_in[6];
    const float* bih1 = (const float*)d_in[7];
    const float* bhh1 = (const float*)d_in[8];
    const float* Wih2 = (const float*)d_in[9];
    const float* Whh2 = (const float*)d_in[10];
    const float* bih2 = (const float*)d_in[11];
    const float* bhh2 = (const float*)d_in[12];
    const float* Wlin = (const float*)d_in[13];
    const float* blin = (const float*)d_in[14];

    float* y  = (float*)d_out;                 // [B,S,1]
    float* hn = y + (size_t)BB * SS;           // [3,B,H]
    float* cn = hn + (size_t)3 * BB * HH;      // [3,B,H]

    float *buf0, *buf1;
    cudaGetSymbolAddress((void**)&buf0, g_buf0);
    cudaGetSymbolAddress((void**)&buf1, g_buf1);

    lstm_scan<true ><<<BB / 2, 256>>>(x,    Wih0, Whh0, bih0, bhh0, buf0,
                                      hn,              cn);
    lstm_scan<false><<<BB / 2, 256>>>(buf0, Wih1, Whh1, bih1, bhh1, buf1,
                                      hn + BB * HH,     cn + BB * HH);
    lstm_scan<false><<<BB / 2, 256>>>(buf1, Wih2, Whh2, bih2, bhh2, buf0,
                                      hn + 2 * BB * HH, cn + 2 * BB * HH);

    proj_kernel<<<(BB * SS) / 8, 256>>>(buf0, Wlin, blin, y);
}